// round 1
// baseline (speedup 1.0000x reference)
#include <cuda_runtime.h>
#include <cuda_bf16.h>
#include <math.h>

#define B 2
#define S 2048
#define D 2048
#define H 16
#define KVH 4
#define HD 128
#define GROUPS (H/KVH)
#define SCALE 0.08838834764831845f

// Scratch (no allocation allowed)
__device__ float g_Q[B*S*H*HD];    // [B,S,H,HD]
__device__ float g_K[B*S*KVH*HD];  // [B,S,KVH,HD]
__device__ float g_V[B*S*KVH*HD];
__device__ float g_O[B*S*H*HD];    // attention out [B,S,H,HD]

// ---------------------------------------------------------------------------
// SGEMM: C[M,N] = A[M,K] @ Bm[K,N], row-major, fp32.
// BM=BN=128, BK=8, 256 threads, 8x8 microtile per thread.
// Requires M%128==0, N%128==0, K%8==0 (true for all our shapes).
// ---------------------------------------------------------------------------
__global__ __launch_bounds__(256) void sgemm_kernel(
    const float* __restrict__ A, const float* __restrict__ Bm,
    float* __restrict__ C, int M, int N, int K)
{
    const int bx = blockIdx.x, by = blockIdx.y;
    const int tid = threadIdx.x;
    __shared__ float As[8][128];
    __shared__ float Bs[8][128];
    const int tx = tid & 15, ty = tid >> 4;
    const int a_row = tid >> 1, a_col = (tid & 1) * 4;
    const int b_row = tid >> 5, b_col = (tid & 31) * 4;
    const float* Ab = A + (size_t)by * 128 * K;
    const float* Bb = Bm + (size_t)bx * 128;
    float acc[8][8];
    #pragma unroll
    for (int i = 0; i < 8; i++)
        #pragma unroll
        for (int j = 0; j < 8; j++) acc[i][j] = 0.f;

    for (int k0 = 0; k0 < K; k0 += 8) {
        float4 av = *reinterpret_cast<const float4*>(Ab + (size_t)a_row * K + k0 + a_col);
        As[a_col + 0][a_row] = av.x;
        As[a_col + 1][a_row] = av.y;
        As[a_col + 2][a_row] = av.z;
        As[a_col + 3][a_row] = av.w;
        float4 bv = *reinterpret_cast<const float4*>(Bb + (size_t)(k0 + b_row) * N + b_col);
        *reinterpret_cast<float4*>(&Bs[b_row][b_col]) = bv;
        __syncthreads();
        #pragma unroll
        for (int kk = 0; kk < 8; kk++) {
            float4 a0 = *reinterpret_cast<const float4*>(&As[kk][ty * 8]);
            float4 a1 = *reinterpret_cast<const float4*>(&As[kk][ty * 8 + 4]);
            float4 b0 = *reinterpret_cast<const float4*>(&Bs[kk][tx * 8]);
            float4 b1 = *reinterpret_cast<const float4*>(&Bs[kk][tx * 8 + 4]);
            float ar[8] = {a0.x, a0.y, a0.z, a0.w, a1.x, a1.y, a1.z, a1.w};
            float br[8] = {b0.x, b0.y, b0.z, b0.w, b1.x, b1.y, b1.z, b1.w};
            #pragma unroll
            for (int i = 0; i < 8; i++)
                #pragma unroll
                for (int j = 0; j < 8; j++)
                    acc[i][j] = fmaf(ar[i], br[j], acc[i][j]);
        }
        __syncthreads();
    }
    float* Cb = C + (size_t)(by * 128 + ty * 8) * N + bx * 128 + tx * 8;
    #pragma unroll
    for (int i = 0; i < 8; i++) {
        *reinterpret_cast<float4*>(Cb + (size_t)i * N) =
            make_float4(acc[i][0], acc[i][1], acc[i][2], acc[i][3]);
        *reinterpret_cast<float4*>(Cb + (size_t)i * N + 4) =
            make_float4(acc[i][4], acc[i][5], acc[i][6], acc[i][7]);
    }
}

// ---------------------------------------------------------------------------
// RoPE (reference semantics): cosf[j] = cos[j>>1] (repeat_interleave(2)),
// rotate_half pairs (j, j+64). In-place on [B,S,nheads,HD].
// One thread per (row, half) pair; handles elements j and j+64.
// ---------------------------------------------------------------------------
__global__ void rope_kernel(float* __restrict__ X,
                            const float* __restrict__ cosb,
                            const float* __restrict__ sinb, int nheads)
{
    int idx = blockIdx.x * blockDim.x + threadIdx.x;  // over B*S*nheads*64
    int half = idx & 63;
    int s = (idx >> 6) / nheads % S;
    size_t base = (size_t)(idx >> 6) * HD;
    float x0 = X[base + half];
    float x1 = X[base + half + 64];
    float c0 = cosb[s * 64 + (half >> 1)];
    float s0 = sinb[s * 64 + (half >> 1)];
    float c1 = cosb[s * 64 + ((half + 64) >> 1)];
    float s1 = sinb[s * 64 + ((half + 64) >> 1)];
    X[base + half]      = x0 * c0 - x1 * s0;
    X[base + half + 64] = x1 * c1 + x0 * s1;
}

// ---------------------------------------------------------------------------
// Causal flash attention, fp32, GQA (kvh = h/GROUPS).
// Tile: 64 queries x 64 keys, HD=128. 128 threads.
// smem: Qs[64][129], KVs (K padded 129 / V stride 128), Ss[64][64], m/l/c[64]
// ---------------------------------------------------------------------------
#define FM 64
#define FN 64
#define QSTR 129
#define FLASH_SMEM ((FM*QSTR + FN*QSTR + FM*FN + 3*FM) * 4)

__global__ __launch_bounds__(128) void flash_kernel(
    const float* __restrict__ Qg, const float* __restrict__ Kg,
    const float* __restrict__ Vg, float* __restrict__ Og)
{
    const int m_tile = blockIdx.x;
    const int h = blockIdx.y;
    const int b = blockIdx.z;
    const int kvh = h / GROUPS;
    const int tid = threadIdx.x;

    extern __shared__ float sm[];
    float* Qs  = sm;                  // FM * QSTR
    float* KVs = Qs + FM * QSTR;      // FN * QSTR (K padded / V stride 128)
    float* Ss  = KVs + FN * QSTR;     // FM * FN
    float* mrow = Ss + FM * FN;
    float* lrow = mrow + FM;
    float* crow = lrow + FM;

    const int m0 = m_tile * FM;

    // load Q tile (padded stride 129 -> scalar stores)
    for (int i = tid; i < FM * HD / 4; i += 128) {
        int r = i >> 5;          // 32 float4 per row
        int dc = (i & 31) * 4;
        float4 v = *reinterpret_cast<const float4*>(
            &Qg[(((size_t)b * S + m0 + r) * H + h) * HD + dc]);
        Qs[r * QSTR + dc + 0] = v.x;
        Qs[r * QSTR + dc + 1] = v.y;
        Qs[r * QSTR + dc + 2] = v.z;
        Qs[r * QSTR + dc + 3] = v.w;
    }
    if (tid < FM) { mrow[tid] = -INFINITY; lrow[tid] = 0.f; }

    const int ty2 = tid >> 4, tx2 = tid & 15;   // PV: rows ty2*8.., cols tx2*8..
    const int tyS = tid >> 3, txS = tid & 7;    // S:  rows tyS*4.., cols txS*8..
    float acc_o[8][8];
    #pragma unroll
    for (int i = 0; i < 8; i++)
        #pragma unroll
        for (int j = 0; j < 8; j++) acc_o[i][j] = 0.f;

    for (int n_tile = 0; n_tile <= m_tile; ++n_tile) {
        const int n0 = n_tile * FN;
        __syncthreads();  // protect KVs from prev PV reads; Q visible (iter 0)

        // load K tile (padded 129, scalar stores)
        for (int i = tid; i < FN * HD / 4; i += 128) {
            int r = i >> 5;
            int dc = (i & 31) * 4;
            float4 v = *reinterpret_cast<const float4*>(
                &Kg[(((size_t)b * S + n0 + r) * KVH + kvh) * HD + dc]);
            KVs[r * QSTR + dc + 0] = v.x;
            KVs[r * QSTR + dc + 1] = v.y;
            KVs[r * QSTR + dc + 2] = v.z;
            KVs[r * QSTR + dc + 3] = v.w;
        }
        __syncthreads();

        // S = Q @ K^T * SCALE  (M=64, N=64, K=128)
        float accs[4][8];
        #pragma unroll
        for (int i = 0; i < 4; i++)
            #pragma unroll
            for (int j = 0; j < 8; j++) accs[i][j] = 0.f;
        for (int d = 0; d < HD; ++d) {
            float ar[4], br[8];
            #pragma unroll
            for (int i = 0; i < 4; i++) ar[i] = Qs[(tyS * 4 + i) * QSTR + d];
            #pragma unroll
            for (int j = 0; j < 8; j++) br[j] = KVs[(txS * 8 + j) * QSTR + d];
            #pragma unroll
            for (int i = 0; i < 4; i++)
                #pragma unroll
                for (int j = 0; j < 8; j++)
                    accs[i][j] = fmaf(ar[i], br[j], accs[i][j]);
        }
        #pragma unroll
        for (int i = 0; i < 4; i++)
            #pragma unroll
            for (int j = 0; j < 8; j++)
                Ss[(tyS * 4 + i) * FN + txS * 8 + j] = accs[i][j] * SCALE;
        __syncthreads();

        // load V tile (stride 128, float4 stores) + per-row online softmax
        for (int i = tid; i < FN * HD / 4; i += 128) {
            int r = i >> 5;
            int dc = (i & 31) * 4;
            float4 v = *reinterpret_cast<const float4*>(
                &Vg[(((size_t)b * S + n0 + r) * KVH + kvh) * HD + dc]);
            *reinterpret_cast<float4*>(&KVs[r * HD + dc]) = v;
        }
        if (tid < FM) {
            int r = tid;
            int q_global = m0 + r;
            int climit = min(FN, q_global - n0 + 1);  // valid keys [0, climit)
            float mprev = mrow[r];
            float mx = mprev;
            for (int c = 0; c < climit; ++c) mx = fmaxf(mx, Ss[r * FN + c]);
            float corr = __expf(mprev - mx);
            float sum = 0.f;
            for (int c = 0; c < FN; ++c) {
                float p = (c < climit) ? __expf(Ss[r * FN + c] - mx) : 0.f;
                Ss[r * FN + c] = p;
                sum += p;
            }
            lrow[r] = lrow[r] * corr + sum;
            mrow[r] = mx;
            crow[r] = corr;
        }
        __syncthreads();

        // O = O*corr + P @ V  (M=64, N=128, K=64)
        #pragma unroll
        for (int i = 0; i < 8; i++) {
            float corr = crow[ty2 * 8 + i];
            #pragma unroll
            for (int j = 0; j < 8; j++) acc_o[i][j] *= corr;
        }
        for (int c = 0; c < FN; ++c) {
            float pr[8];
            #pragma unroll
            for (int i = 0; i < 8; i++) pr[i] = Ss[(ty2 * 8 + i) * FN + c];
            float4 v0 = *reinterpret_cast<const float4*>(&KVs[c * HD + tx2 * 8]);
            float4 v1 = *reinterpret_cast<const float4*>(&KVs[c * HD + tx2 * 8 + 4]);
            float vr[8] = {v0.x, v0.y, v0.z, v0.w, v1.x, v1.y, v1.z, v1.w};
            #pragma unroll
            for (int i = 0; i < 8; i++)
                #pragma unroll
                for (int j = 0; j < 8; j++)
                    acc_o[i][j] = fmaf(pr[i], vr[j], acc_o[i][j]);
        }
    }

    // epilogue: normalize and store [B,S,H,HD]
    #pragma unroll
    for (int i = 0; i < 8; i++) {
        int r = ty2 * 8 + i;
        float inv = 1.f / lrow[r];
        size_t obase = (((size_t)b * S + m0 + r) * H + h) * HD + tx2 * 8;
        float4 o0 = make_float4(acc_o[i][0] * inv, acc_o[i][1] * inv,
                                acc_o[i][2] * inv, acc_o[i][3] * inv);
        float4 o1 = make_float4(acc_o[i][4] * inv, acc_o[i][5] * inv,
                                acc_o[i][6] * inv, acc_o[i][7] * inv);
        *reinterpret_cast<float4*>(&Og[obase]) = o0;
        *reinterpret_cast<float4*>(&Og[obase + 4]) = o1;
    }
}

// ---------------------------------------------------------------------------
extern "C" void kernel_launch(void* const* d_in, const int* in_sizes, int n_in,
                              void* d_out, int out_size)
{
    const float* x    = (const float*)d_in[0];
    const float* cosb = (const float*)d_in[1];
    const float* sinb = (const float*)d_in[2];
    // d_in[3] = mask (causal, static -> unused)
    const float* Wq   = (const float*)d_in[4];
    const float* Wk   = (const float*)d_in[5];
    const float* Wv   = (const float*)d_in[6];
    const float* Wo   = (const float*)d_in[7];
    float* out = (float*)d_out;

    float *Qp, *Kp, *Vp, *Op;
    cudaGetSymbolAddress((void**)&Qp, g_Q);
    cudaGetSymbolAddress((void**)&Kp, g_K);
    cudaGetSymbolAddress((void**)&Vp, g_V);
    cudaGetSymbolAddress((void**)&Op, g_O);

    const int M = B * S;  // 4096

    // QKV projections
    sgemm_kernel<<<dim3((H * HD) / 128, M / 128), 256>>>(x, Wq, Qp, M, H * HD, D);
    sgemm_kernel<<<dim3((KVH * HD) / 128, M / 128), 256>>>(x, Wk, Kp, M, KVH * HD, D);
    sgemm_kernel<<<dim3((KVH * HD) / 128, M / 128), 256>>>(x, Wv, Vp, M, KVH * HD, D);

    // RoPE
    rope_kernel<<<(B * S * H * 64) / 256, 256>>>(Qp, cosb, sinb, H);
    rope_kernel<<<(B * S * KVH * 64) / 256, 256>>>(Kp, cosb, sinb, KVH);

    // Causal GQA flash attention
    cudaFuncSetAttribute(flash_kernel, cudaFuncAttributeMaxDynamicSharedMemorySize,
                         FLASH_SMEM);
    flash_kernel<<<dim3(S / FM, H, B), 128, FLASH_SMEM>>>(Qp, Kp, Vp, Op);

    // Output projection
    sgemm_kernel<<<dim3(D / 128, M / 128), 256>>>(Op, Wo, out, M, D, D);
}

// round 4
// speedup vs baseline: 1.5629x; 1.5629x over previous
#include <cuda_runtime.h>
#include <cuda_bf16.h>
#include <math.h>
#include <stdint.h>

#define B 2
#define S 2048
#define D 2048
#define H 16
#define KVH 4
#define HD 128
#define GROUPS (H/KVH)
#define SCALE 0.08838834764831845f
#define M_ROWS (B*S)          // 4096

// ---------------- scratch (__device__ globals; no allocation) --------------
__device__ float g_Q[B*S*H*HD];
__device__ float g_K[B*S*KVH*HD];
__device__ float g_V[B*S*KVH*HD];
__device__ float g_O[B*S*H*HD];

__device__ __nv_bfloat16 g_xhi[M_ROWS*D],  g_xlo[M_ROWS*D];
__device__ __nv_bfloat16 g_ohi[M_ROWS*D],  g_olo[M_ROWS*D];
__device__ __nv_bfloat16 g_WqT_hi[D*H*HD],   g_WqT_lo[D*H*HD];     // [N,K] row-major
__device__ __nv_bfloat16 g_WkT_hi[D*KVH*HD], g_WkT_lo[D*KVH*HD];
__device__ __nv_bfloat16 g_WvT_hi[D*KVH*HD], g_WvT_lo[D*KVH*HD];
__device__ __nv_bfloat16 g_WoT_hi[D*H*HD],   g_WoT_lo[D*H*HD];

// ---------------------------- helpers --------------------------------------
__device__ __forceinline__ uint32_t smem_u32(const void* p) {
    uint32_t a;
    asm("{ .reg .u64 t; cvta.to.shared.u64 t, %1; cvt.u32.u64 %0, t; }"
        : "=r"(a) : "l"(p));
    return a;
}
__device__ __forceinline__ void cp16(uint32_t s, const void* g) {
    asm volatile("cp.async.cg.shared.global [%0], [%1], 16;" :: "r"(s), "l"(g));
}
#define CP_COMMIT() asm volatile("cp.async.commit_group;" ::: "memory")
#define CP_WAIT(n)  asm volatile("cp.async.wait_group %0;" :: "n"(n) : "memory")

__device__ __forceinline__ void mma16816(float* c, const uint32_t* a,
                                         const uint32_t* b) {
    asm volatile(
        "mma.sync.aligned.m16n8k16.row.col.f32.bf16.bf16.f32 "
        "{%0,%1,%2,%3}, {%4,%5,%6,%7}, {%8,%9}, {%0,%1,%2,%3};"
        : "+f"(c[0]), "+f"(c[1]), "+f"(c[2]), "+f"(c[3])
        : "r"(a[0]), "r"(a[1]), "r"(a[2]), "r"(a[3]), "r"(b[0]), "r"(b[1]));
}

// ---------------------------------------------------------------------------
// split: fp32 -> (hi, lo) bf16
// ---------------------------------------------------------------------------
__global__ void split_kernel(const float* __restrict__ X,
                             __nv_bfloat16* __restrict__ hi,
                             __nv_bfloat16* __restrict__ lo, int n4)
{
    int i = blockIdx.x * blockDim.x + threadIdx.x;
    if (i >= n4) return;
    float4 x = reinterpret_cast<const float4*>(X)[i];
    __nv_bfloat16 h[4], l[4];
    float xs[4] = {x.x, x.y, x.z, x.w};
    #pragma unroll
    for (int k = 0; k < 4; k++) {
        h[k] = __float2bfloat16_rn(xs[k]);
        l[k] = __float2bfloat16_rn(xs[k] - __bfloat162float(h[k]));
    }
    *reinterpret_cast<uint2*>(hi + 4*(size_t)i) = *reinterpret_cast<uint2*>(h);
    *reinterpret_cast<uint2*>(lo + 4*(size_t)i) = *reinterpret_cast<uint2*>(l);
}

// ---------------------------------------------------------------------------
// transpose + split: W [R, C] fp32 row-major -> T{hi,lo} [C, R] bf16
// ---------------------------------------------------------------------------
__global__ void transpose_split_kernel(const float* __restrict__ W,
                                       __nv_bfloat16* __restrict__ Thi,
                                       __nv_bfloat16* __restrict__ Tlo,
                                       int R, int C)
{
    __shared__ float t[32][33];
    int c0 = blockIdx.x * 32, r0 = blockIdx.y * 32;
    int tx = threadIdx.x, ty = threadIdx.y;   // 32 x 8
    #pragma unroll
    for (int i = 0; i < 32; i += 8)
        t[ty + i][tx] = W[(size_t)(r0 + ty + i) * C + c0 + tx];
    __syncthreads();
    #pragma unroll
    for (int i = 0; i < 32; i += 8) {
        float x = t[tx][ty + i];
        size_t o = (size_t)(c0 + ty + i) * R + r0 + tx;
        __nv_bfloat16 h = __float2bfloat16_rn(x);
        Thi[o] = h;
        Tlo[o] = __float2bfloat16_rn(x - __bfloat162float(h));
    }
}

// ---------------------------------------------------------------------------
// HMMA bf16x3 GEMM: C[M,N] = (Ahi+Alo)[M,K] @ (Bhi+Blo)^T, B stored [N,K].
// CTA 128x128, BK=64, 8 warps (2x4), warp tile 64x32, m16n8k16.
// 2-stage cp.async pipeline. Smem row stride 72 bf16 (conflict-free).
// ---------------------------------------------------------------------------
#define ASTR 72
#define MAT_SZ (128*ASTR)          // bf16 units per matrix buffer
#define STG_SZ (4*MAT_SZ)          // 4 matrices (Ahi,Alo,Bhi,Blo) per stage
#define GEMM_SMEM (2*STG_SZ*2)     // bytes

__global__ __launch_bounds__(256, 1)
void gemm_bf16x3_kernel(float* __restrict__ C,
    const __nv_bfloat16* __restrict__ Ahi, const __nv_bfloat16* __restrict__ Alo,
    const __nv_bfloat16* __restrict__ Bhi, const __nv_bfloat16* __restrict__ Blo,
    int M, int N, int K)
{
    extern __shared__ __nv_bfloat16 smb[];
    const uint32_t smem_base = smem_u32(smb);
    const int tid = threadIdx.x;
    const int wid = tid >> 5, lane = tid & 31;
    const int g = lane >> 2, tig = lane & 3;
    const int wm = wid >> 2, wn = wid & 3;        // 2 x 4 warp grid
    const int m0 = blockIdx.y * 128, n0 = blockIdx.x * 128;
    const int nch = K >> 6;

    const __nv_bfloat16* gsrc[4] = {Ahi, Alo, Bhi, Blo};

    // async-load one 64-wide K chunk into a stage: 4 matrices x 128 rows x 8 x 16B
    auto load_chunk = [&](int c, int stage) {
        const int k0 = c << 6;
        #pragma unroll
        for (int i = 0; i < 16; ++i) {
            int v = i * 256 + tid;            // 0..4095
            int mat = v >> 10;                // 0..3
            int r = (v >> 3) & 127;
            int ch = v & 7;
            int grow = (mat < 2 ? m0 : n0) + r;
            const __nv_bfloat16* src = gsrc[mat] + (size_t)grow * K + k0 + ch * 8;
            uint32_t dst = smem_base +
                (uint32_t)(stage * STG_SZ + mat * MAT_SZ + r * ASTR + ch * 8) * 2;
            cp16(dst, src);
        }
    };

    float acc[4][4][4];
    #pragma unroll
    for (int mi = 0; mi < 4; mi++)
        #pragma unroll
        for (int ni = 0; ni < 4; ni++)
            #pragma unroll
            for (int r = 0; r < 4; r++) acc[mi][ni][r] = 0.f;

    load_chunk(0, 0);
    CP_COMMIT();

    for (int c = 0; c < nch; ++c) {
        if (c + 1 < nch) { load_chunk(c + 1, (c + 1) & 1); CP_COMMIT(); CP_WAIT(1); }
        else             { CP_WAIT(0); }
        __syncthreads();

        const __nv_bfloat16* A0 = smb + (c & 1) * STG_SZ;             // Ahi
        const __nv_bfloat16* A1 = A0 + MAT_SZ;                        // Alo
        const __nv_bfloat16* B0 = A0 + 2 * MAT_SZ;                    // Bhi
        const __nv_bfloat16* B1 = A0 + 3 * MAT_SZ;                    // Blo

        #pragma unroll
        for (int ks = 0; ks < 4; ++ks) {
            const int kk = ks * 16 + 2 * tig;
            uint32_t ahi[4][4], alo[4][4], bhi[4][2], blo[4][2];
            #pragma unroll
            for (int mi = 0; mi < 4; ++mi) {
                int rm = wm * 64 + mi * 16 + g;
                ahi[mi][0] = *(const uint32_t*)(A0 + rm * ASTR + kk);
                ahi[mi][1] = *(const uint32_t*)(A0 + (rm + 8) * ASTR + kk);
                ahi[mi][2] = *(const uint32_t*)(A0 + rm * ASTR + kk + 8);
                ahi[mi][3] = *(const uint32_t*)(A0 + (rm + 8) * ASTR + kk + 8);
                alo[mi][0] = *(const uint32_t*)(A1 + rm * ASTR + kk);
                alo[mi][1] = *(const uint32_t*)(A1 + (rm + 8) * ASTR + kk);
                alo[mi][2] = *(const uint32_t*)(A1 + rm * ASTR + kk + 8);
                alo[mi][3] = *(const uint32_t*)(A1 + (rm + 8) * ASTR + kk + 8);
            }
            #pragma unroll
            for (int ni = 0; ni < 4; ++ni) {
                int cn = wn * 32 + ni * 8 + g;
                bhi[ni][0] = *(const uint32_t*)(B0 + cn * ASTR + kk);
                bhi[ni][1] = *(const uint32_t*)(B0 + cn * ASTR + kk + 8);
                blo[ni][0] = *(const uint32_t*)(B1 + cn * ASTR + kk);
                blo[ni][1] = *(const uint32_t*)(B1 + cn * ASTR + kk + 8);
            }
            #pragma unroll
            for (int mi = 0; mi < 4; ++mi)
                #pragma unroll
                for (int ni = 0; ni < 4; ++ni) {
                    mma16816(acc[mi][ni], ahi[mi], bhi[ni]);
                    mma16816(acc[mi][ni], ahi[mi], blo[ni]);
                    mma16816(acc[mi][ni], alo[mi], bhi[ni]);
                }
        }
        __syncthreads();
    }

    // epilogue: C fp32 row-major
    #pragma unroll
    for (int mi = 0; mi < 4; ++mi) {
        int rm = m0 + wm * 64 + mi * 16 + g;
        #pragma unroll
        for (int ni = 0; ni < 4; ++ni) {
            int cn = n0 + wn * 32 + ni * 8 + 2 * tig;
            *(float2*)(C + (size_t)rm * N + cn) =
                make_float2(acc[mi][ni][0], acc[mi][ni][1]);
            *(float2*)(C + (size_t)(rm + 8) * N + cn) =
                make_float2(acc[mi][ni][2], acc[mi][ni][3]);
        }
    }
}

// ---------------------------------------------------------------------------
// RoPE (reference semantics)
// ---------------------------------------------------------------------------
__global__ void rope_kernel(float* __restrict__ X,
                            const float* __restrict__ cosb,
                            const float* __restrict__ sinb, int nheads)
{
    int idx = blockIdx.x * blockDim.x + threadIdx.x;
    int half = idx & 63;
    int s = (idx >> 6) / nheads % S;
    size_t base = (size_t)(idx >> 6) * HD;
    float x0 = X[base + half];
    float x1 = X[base + half + 64];
    float c0 = cosb[s * 64 + (half >> 1)];
    float s0 = sinb[s * 64 + (half >> 1)];
    float c1 = cosb[s * 64 + ((half + 64) >> 1)];
    float s1 = sinb[s * 64 + ((half + 64) >> 1)];
    X[base + half]      = x0 * c0 - x1 * s0;
    X[base + half + 64] = x1 * c1 + x0 * s1;
}

// ---------------------------------------------------------------------------
// Causal flash attention, fp32, GQA (unchanged)
// ---------------------------------------------------------------------------
#define FM 64
#define FN 64
#define QSTR 129
#define FLASH_SMEM ((FM*QSTR + FN*QSTR + FM*FN + 3*FM) * 4)

__global__ __launch_bounds__(128) void flash_kernel(
    const float* __restrict__ Qg, const float* __restrict__ Kg,
    const float* __restrict__ Vg, float* __restrict__ Og)
{
    const int m_tile = blockIdx.x;
    const int h = blockIdx.y;
    const int b = blockIdx.z;
    const int kvh = h / GROUPS;
    const int tid = threadIdx.x;

    extern __shared__ float smf[];
    float* Qs  = smf;
    float* KVs = Qs + FM * QSTR;
    float* Ss  = KVs + FN * QSTR;
    float* mrow = Ss + FM * FN;
    float* lrow = mrow + FM;
    float* crow = lrow + FM;

    const int m0 = m_tile * FM;

    for (int i = tid; i < FM * HD / 4; i += 128) {
        int r = i >> 5;
        int dc = (i & 31) * 4;
        float4 v = *reinterpret_cast<const float4*>(
            &Qg[(((size_t)b * S + m0 + r) * H + h) * HD + dc]);
        Qs[r * QSTR + dc + 0] = v.x;
        Qs[r * QSTR + dc + 1] = v.y;
        Qs[r * QSTR + dc + 2] = v.z;
        Qs[r * QSTR + dc + 3] = v.w;
    }
    if (tid < FM) { mrow[tid] = -INFINITY; lrow[tid] = 0.f; }

    const int ty2 = tid >> 4, tx2 = tid & 15;
    const int tyS = tid >> 3, txS = tid & 7;
    float acc_o[8][8];
    #pragma unroll
    for (int i = 0; i < 8; i++)
        #pragma unroll
        for (int j = 0; j < 8; j++) acc_o[i][j] = 0.f;

    for (int n_tile = 0; n_tile <= m_tile; ++n_tile) {
        const int n0 = n_tile * FN;
        __syncthreads();

        for (int i = tid; i < FN * HD / 4; i += 128) {
            int r = i >> 5;
            int dc = (i & 31) * 4;
            float4 v = *reinterpret_cast<const float4*>(
                &Kg[(((size_t)b * S + n0 + r) * KVH + kvh) * HD + dc]);
            KVs[r * QSTR + dc + 0] = v.x;
            KVs[r * QSTR + dc + 1] = v.y;
            KVs[r * QSTR + dc + 2] = v.z;
            KVs[r * QSTR + dc + 3] = v.w;
        }
        __syncthreads();

        float accs[4][8];
        #pragma unroll
        for (int i = 0; i < 4; i++)
            #pragma unroll
            for (int j = 0; j < 8; j++) accs[i][j] = 0.f;
        for (int d = 0; d < HD; ++d) {
            float ar[4], br[8];
            #pragma unroll
            for (int i = 0; i < 4; i++) ar[i] = Qs[(tyS * 4 + i) * QSTR + d];
            #pragma unroll
            for (int j = 0; j < 8; j++) br[j] = KVs[(txS * 8 + j) * QSTR + d];
            #pragma unroll
            for (int i = 0; i < 4; i++)
                #pragma unroll
                for (int j = 0; j < 8; j++)
                    accs[i][j] = fmaf(ar[i], br[j], accs[i][j]);
        }
        #pragma unroll
        for (int i = 0; i < 4; i++)
            #pragma unroll
            for (int j = 0; j < 8; j++)
                Ss[(tyS * 4 + i) * FN + txS * 8 + j] = accs[i][j] * SCALE;
        __syncthreads();

        for (int i = tid; i < FN * HD / 4; i += 128) {
            int r = i >> 5;
            int dc = (i & 31) * 4;
            float4 v = *reinterpret_cast<const float4*>(
                &Vg[(((size_t)b * S + n0 + r) * KVH + kvh) * HD + dc]);
            *reinterpret_cast<float4*>(&KVs[r * HD + dc]) = v;
        }
        if (tid < FM) {
            int r = tid;
            int q_global = m0 + r;
            int climit = min(FN, q_global - n0 + 1);
            float mprev = mrow[r];
            float mx = mprev;
            for (int c = 0; c < climit; ++c) mx = fmaxf(mx, Ss[r * FN + c]);
            float corr = __expf(mprev - mx);
            float sum = 0.f;
            for (int c = 0; c < FN; ++c) {
                float p = (c < climit) ? __expf(Ss[r * FN + c] - mx) : 0.f;
                Ss[r * FN + c] = p;
                sum += p;
            }
            lrow[r] = lrow[r] * corr + sum;
            mrow[r] = mx;
            crow[r] = corr;
        }
        __syncthreads();

        #pragma unroll
        for (int i = 0; i < 8; i++) {
            float corr = crow[ty2 * 8 + i];
            #pragma unroll
            for (int j = 0; j < 8; j++) acc_o[i][j] *= corr;
        }
        for (int c = 0; c < FN; ++c) {
            float pr[8];
            #pragma unroll
            for (int i = 0; i < 8; i++) pr[i] = Ss[(ty2 * 8 + i) * FN + c];
            float4 v0 = *reinterpret_cast<const float4*>(&KVs[c * HD + tx2 * 8]);
            float4 v1 = *reinterpret_cast<const float4*>(&KVs[c * HD + tx2 * 8 + 4]);
            float vr[8] = {v0.x, v0.y, v0.z, v0.w, v1.x, v1.y, v1.z, v1.w};
            #pragma unroll
            for (int i = 0; i < 8; i++)
                #pragma unroll
                for (int j = 0; j < 8; j++)
                    acc_o[i][j] = fmaf(pr[i], vr[j], acc_o[i][j]);
        }
    }

    #pragma unroll
    for (int i = 0; i < 8; i++) {
        int r = ty2 * 8 + i;
        float inv = 1.f / lrow[r];
        size_t obase = (((size_t)b * S + m0 + r) * H + h) * HD + tx2 * 8;
        *reinterpret_cast<float4*>(&Og[obase]) = make_float4(
            acc_o[i][0] * inv, acc_o[i][1] * inv, acc_o[i][2] * inv, acc_o[i][3] * inv);
        *reinterpret_cast<float4*>(&Og[obase + 4]) = make_float4(
            acc_o[i][4] * inv, acc_o[i][5] * inv, acc_o[i][6] * inv, acc_o[i][7] * inv);
    }
}

// ---------------------------------------------------------------------------
extern "C" void kernel_launch(void* const* d_in, const int* in_sizes, int n_in,
                              void* d_out, int out_size)
{
    const float* x    = (const float*)d_in[0];
    const float* cosb = (const float*)d_in[1];
    const float* sinb = (const float*)d_in[2];
    const float* Wq   = (const float*)d_in[4];
    const float* Wk   = (const float*)d_in[5];
    const float* Wv   = (const float*)d_in[6];
    const float* Wo   = (const float*)d_in[7];
    float* out = (float*)d_out;

    float *Qp, *Kp, *Vp, *Op;
    cudaGetSymbolAddress((void**)&Qp, g_Q);
    cudaGetSymbolAddress((void**)&Kp, g_K);
    cudaGetSymbolAddress((void**)&Vp, g_V);
    cudaGetSymbolAddress((void**)&Op, g_O);
    __nv_bfloat16 *xhi, *xlo, *ohi, *olo;
    __nv_bfloat16 *wqh, *wql, *wkh, *wkl, *wvh, *wvl, *woh, *wol;
    cudaGetSymbolAddress((void**)&xhi, g_xhi);
    cudaGetSymbolAddress((void**)&xlo, g_xlo);
    cudaGetSymbolAddress((void**)&ohi, g_ohi);
    cudaGetSymbolAddress((void**)&olo, g_olo);
    cudaGetSymbolAddress((void**)&wqh, g_WqT_hi);
    cudaGetSymbolAddress((void**)&wql, g_WqT_lo);
    cudaGetSymbolAddress((void**)&wkh, g_WkT_hi);
    cudaGetSymbolAddress((void**)&wkl, g_WkT_lo);
    cudaGetSymbolAddress((void**)&wvh, g_WvT_hi);
    cudaGetSymbolAddress((void**)&wvl, g_WvT_lo);
    cudaGetSymbolAddress((void**)&woh, g_WoT_hi);
    cudaGetSymbolAddress((void**)&wol, g_WoT_lo);

    const int M = M_ROWS;  // 4096

    // split inputs / transpose+split weights
    split_kernel<<<(M * D / 4) / 256, 256>>>(x, xhi, xlo, M * D / 4);
    transpose_split_kernel<<<dim3(D / 32, D / 32), dim3(32, 8)>>>(Wq, wqh, wql, D, H * HD);
    transpose_split_kernel<<<dim3((KVH * HD) / 32, D / 32), dim3(32, 8)>>>(Wk, wkh, wkl, D, KVH * HD);
    transpose_split_kernel<<<dim3((KVH * HD) / 32, D / 32), dim3(32, 8)>>>(Wv, wvh, wvl, D, KVH * HD);
    transpose_split_kernel<<<dim3(D / 32, (H * HD) / 32), dim3(32, 8)>>>(Wo, woh, wol, H * HD, D);

    cudaFuncSetAttribute(gemm_bf16x3_kernel,
                         cudaFuncAttributeMaxDynamicSharedMemorySize, GEMM_SMEM);

    // QKV projections on HMMA tensor cores
    gemm_bf16x3_kernel<<<dim3((H * HD) / 128, M / 128), 256, GEMM_SMEM>>>(
        Qp, xhi, xlo, wqh, wql, M, H * HD, D);
    gemm_bf16x3_kernel<<<dim3((KVH * HD) / 128, M / 128), 256, GEMM_SMEM>>>(
        Kp, xhi, xlo, wkh, wkl, M, KVH * HD, D);
    gemm_bf16x3_kernel<<<dim3((KVH * HD) / 128, M / 128), 256, GEMM_SMEM>>>(
        Vp, xhi, xlo, wvh, wvl, M, KVH * HD, D);

    // RoPE
    rope_kernel<<<(B * S * H * 64) / 256, 256>>>(Qp, cosb, sinb, H);
    rope_kernel<<<(B * S * KVH * 64) / 256, 256>>>(Kp, cosb, sinb, KVH);

    // Causal GQA flash attention (fp32)
    cudaFuncSetAttribute(flash_kernel, cudaFuncAttributeMaxDynamicSharedMemorySize,
                         FLASH_SMEM);
    flash_kernel<<<dim3(S / FM, H, B), 128, FLASH_SMEM>>>(Qp, Kp, Vp, Op);

    // Output projection on HMMA tensor cores
    split_kernel<<<(M * D / 4) / 256, 256>>>(Op, ohi, olo, M * D / 4);
    gemm_bf16x3_kernel<<<dim3(D / 128, M / 128), 256, GEMM_SMEM>>>(
        out, ohi, olo, woh, wol, M, D, D);
}

// round 5
// speedup vs baseline: 2.9086x; 1.8611x over previous
#include <cuda_runtime.h>
#include <cuda_bf16.h>
#include <math.h>
#include <stdint.h>

#define B 2
#define S 2048
#define D 2048
#define H 16
#define KVH 4
#define HD 128
#define GROUPS (H/KVH)
#define SCALE 0.08838834764831845f
#define M_ROWS (B*S)          // 4096

// ---------------- scratch (__device__ globals; no allocation) --------------
__device__ float g_Q[B*S*H*HD];
__device__ float g_K[B*S*KVH*HD];
__device__ float g_V[B*S*KVH*HD];
__device__ float g_O[B*S*H*HD];

__device__ __nv_bfloat16 g_xhi[M_ROWS*D],  g_xlo[M_ROWS*D];
__device__ __nv_bfloat16 g_ohi[M_ROWS*D],  g_olo[M_ROWS*D];
__device__ __nv_bfloat16 g_WqT_hi[D*H*HD],   g_WqT_lo[D*H*HD];
__device__ __nv_bfloat16 g_WkT_hi[D*KVH*HD], g_WkT_lo[D*KVH*HD];
__device__ __nv_bfloat16 g_WvT_hi[D*KVH*HD], g_WvT_lo[D*KVH*HD];
__device__ __nv_bfloat16 g_WoT_hi[D*H*HD],   g_WoT_lo[D*H*HD];

__device__ __nv_bfloat16 g_Qhi[B*S*H*HD],   g_Qlo[B*S*H*HD];
__device__ __nv_bfloat16 g_Khi[B*S*KVH*HD], g_Klo[B*S*KVH*HD];
__device__ __nv_bfloat16 g_Vhi[B*S*KVH*HD], g_Vlo[B*S*KVH*HD];

// ---------------------------- helpers --------------------------------------
__device__ __forceinline__ uint32_t smem_u32(const void* p) {
    uint32_t a;
    asm("{ .reg .u64 t; cvta.to.shared.u64 t, %1; cvt.u32.u64 %0, t; }"
        : "=r"(a) : "l"(p));
    return a;
}
__device__ __forceinline__ void cp16(uint32_t s, const void* g) {
    asm volatile("cp.async.cg.shared.global [%0], [%1], 16;" :: "r"(s), "l"(g));
}
#define CP_COMMIT() asm volatile("cp.async.commit_group;" ::: "memory")
#define CP_WAIT(n)  asm volatile("cp.async.wait_group %0;" :: "n"(n) : "memory")

__device__ __forceinline__ void mma16816(float* c, const uint32_t* a,
                                         const uint32_t* b) {
    asm volatile(
        "mma.sync.aligned.m16n8k16.row.col.f32.bf16.bf16.f32 "
        "{%0,%1,%2,%3}, {%4,%5,%6,%7}, {%8,%9}, {%0,%1,%2,%3};"
        : "+f"(c[0]), "+f"(c[1]), "+f"(c[2]), "+f"(c[3])
        : "r"(a[0]), "r"(a[1]), "r"(a[2]), "r"(a[3]), "r"(b[0]), "r"(b[1]));
}
__device__ __forceinline__ void ldmx4t(uint32_t* r, uint32_t addr) {
    asm volatile("ldmatrix.sync.aligned.m8n8.x4.trans.shared.b16 "
                 "{%0,%1,%2,%3}, [%4];"
        : "=r"(r[0]), "=r"(r[1]), "=r"(r[2]), "=r"(r[3]) : "r"(addr));
}

// ---------------------------------------------------------------------------
// split kernels
// ---------------------------------------------------------------------------
__global__ void split_kernel(const float* __restrict__ X,
                             __nv_bfloat16* __restrict__ hi,
                             __nv_bfloat16* __restrict__ lo, int n4)
{
    int i = blockIdx.x * blockDim.x + threadIdx.x;
    if (i >= n4) return;
    float4 x = reinterpret_cast<const float4*>(X)[i];
    __nv_bfloat16 h[4], l[4];
    float xs[4] = {x.x, x.y, x.z, x.w};
    #pragma unroll
    for (int k = 0; k < 4; k++) {
        h[k] = __float2bfloat16_rn(xs[k]);
        l[k] = __float2bfloat16_rn(xs[k] - __bfloat162float(h[k]));
    }
    *reinterpret_cast<uint2*>(hi + 4*(size_t)i) = *reinterpret_cast<uint2*>(h);
    *reinterpret_cast<uint2*>(lo + 4*(size_t)i) = *reinterpret_cast<uint2*>(l);
}

__global__ void split_scale_kernel(const float* __restrict__ X,
                                   __nv_bfloat16* __restrict__ hi,
                                   __nv_bfloat16* __restrict__ lo,
                                   float scale, int n4)
{
    int i = blockIdx.x * blockDim.x + threadIdx.x;
    if (i >= n4) return;
    float4 x = reinterpret_cast<const float4*>(X)[i];
    __nv_bfloat16 h[4], l[4];
    float xs[4] = {x.x * scale, x.y * scale, x.z * scale, x.w * scale};
    #pragma unroll
    for (int k = 0; k < 4; k++) {
        h[k] = __float2bfloat16_rn(xs[k]);
        l[k] = __float2bfloat16_rn(xs[k] - __bfloat162float(h[k]));
    }
    *reinterpret_cast<uint2*>(hi + 4*(size_t)i) = *reinterpret_cast<uint2*>(h);
    *reinterpret_cast<uint2*>(lo + 4*(size_t)i) = *reinterpret_cast<uint2*>(l);
}

// ---------------------------------------------------------------------------
// transpose + split: W [R, C] fp32 row-major -> T{hi,lo} [C, R] bf16
// ---------------------------------------------------------------------------
__global__ void transpose_split_kernel(const float* __restrict__ W,
                                       __nv_bfloat16* __restrict__ Thi,
                                       __nv_bfloat16* __restrict__ Tlo,
                                       int R, int C)
{
    __shared__ float t[32][33];
    int c0 = blockIdx.x * 32, r0 = blockIdx.y * 32;
    int tx = threadIdx.x, ty = threadIdx.y;
    #pragma unroll
    for (int i = 0; i < 32; i += 8)
        t[ty + i][tx] = W[(size_t)(r0 + ty + i) * C + c0 + tx];
    __syncthreads();
    #pragma unroll
    for (int i = 0; i < 32; i += 8) {
        float x = t[tx][ty + i];
        size_t o = (size_t)(c0 + ty + i) * R + r0 + tx;
        __nv_bfloat16 h = __float2bfloat16_rn(x);
        Thi[o] = h;
        Tlo[o] = __float2bfloat16_rn(x - __bfloat162float(h));
    }
}

// ---------------------------------------------------------------------------
// HMMA bf16x3 GEMM (unchanged from R4)
// ---------------------------------------------------------------------------
#define ASTR 72
#define MAT_SZ (128*ASTR)
#define STG_SZ (4*MAT_SZ)
#define GEMM_SMEM (2*STG_SZ*2)

__global__ __launch_bounds__(256, 1)
void gemm_bf16x3_kernel(float* __restrict__ C,
    const __nv_bfloat16* __restrict__ Ahi, const __nv_bfloat16* __restrict__ Alo,
    const __nv_bfloat16* __restrict__ Bhi, const __nv_bfloat16* __restrict__ Blo,
    int M, int N, int K)
{
    extern __shared__ __nv_bfloat16 smb[];
    const uint32_t smem_base = smem_u32(smb);
    const int tid = threadIdx.x;
    const int wid = tid >> 5, lane = tid & 31;
    const int g = lane >> 2, tig = lane & 3;
    const int wm = wid >> 2, wn = wid & 3;
    const int m0 = blockIdx.y * 128, n0 = blockIdx.x * 128;
    const int nch = K >> 6;

    const __nv_bfloat16* gsrc[4] = {Ahi, Alo, Bhi, Blo};

    auto load_chunk = [&](int c, int stage) {
        const int k0 = c << 6;
        #pragma unroll
        for (int i = 0; i < 16; ++i) {
            int v = i * 256 + tid;
            int mat = v >> 10;
            int r = (v >> 3) & 127;
            int ch = v & 7;
            int grow = (mat < 2 ? m0 : n0) + r;
            const __nv_bfloat16* src = gsrc[mat] + (size_t)grow * K + k0 + ch * 8;
            uint32_t dst = smem_base +
                (uint32_t)(stage * STG_SZ + mat * MAT_SZ + r * ASTR + ch * 8) * 2;
            cp16(dst, src);
        }
    };

    float acc[4][4][4];
    #pragma unroll
    for (int mi = 0; mi < 4; mi++)
        #pragma unroll
        for (int ni = 0; ni < 4; ni++)
            #pragma unroll
            for (int r = 0; r < 4; r++) acc[mi][ni][r] = 0.f;

    load_chunk(0, 0);
    CP_COMMIT();

    for (int c = 0; c < nch; ++c) {
        if (c + 1 < nch) { load_chunk(c + 1, (c + 1) & 1); CP_COMMIT(); CP_WAIT(1); }
        else             { CP_WAIT(0); }
        __syncthreads();

        const __nv_bfloat16* A0 = smb + (c & 1) * STG_SZ;
        const __nv_bfloat16* A1 = A0 + MAT_SZ;
        const __nv_bfloat16* B0 = A0 + 2 * MAT_SZ;
        const __nv_bfloat16* B1 = A0 + 3 * MAT_SZ;

        #pragma unroll
        for (int ks = 0; ks < 4; ++ks) {
            const int kk = ks * 16 + 2 * tig;
            uint32_t ahi[4][4], alo[4][4], bhi[4][2], blo[4][2];
            #pragma unroll
            for (int mi = 0; mi < 4; ++mi) {
                int rm = wm * 64 + mi * 16 + g;
                ahi[mi][0] = *(const uint32_t*)(A0 + rm * ASTR + kk);
                ahi[mi][1] = *(const uint32_t*)(A0 + (rm + 8) * ASTR + kk);
                ahi[mi][2] = *(const uint32_t*)(A0 + rm * ASTR + kk + 8);
                ahi[mi][3] = *(const uint32_t*)(A0 + (rm + 8) * ASTR + kk + 8);
                alo[mi][0] = *(const uint32_t*)(A1 + rm * ASTR + kk);
                alo[mi][1] = *(const uint32_t*)(A1 + (rm + 8) * ASTR + kk);
                alo[mi][2] = *(const uint32_t*)(A1 + rm * ASTR + kk + 8);
                alo[mi][3] = *(const uint32_t*)(A1 + (rm + 8) * ASTR + kk + 8);
            }
            #pragma unroll
            for (int ni = 0; ni < 4; ++ni) {
                int cn = wn * 32 + ni * 8 + g;
                bhi[ni][0] = *(const uint32_t*)(B0 + cn * ASTR + kk);
                bhi[ni][1] = *(const uint32_t*)(B0 + cn * ASTR + kk + 8);
                blo[ni][0] = *(const uint32_t*)(B1 + cn * ASTR + kk);
                blo[ni][1] = *(const uint32_t*)(B1 + cn * ASTR + kk + 8);
            }
            #pragma unroll
            for (int mi = 0; mi < 4; ++mi)
                #pragma unroll
                for (int ni = 0; ni < 4; ++ni) {
                    mma16816(acc[mi][ni], ahi[mi], bhi[ni]);
                    mma16816(acc[mi][ni], ahi[mi], blo[ni]);
                    mma16816(acc[mi][ni], alo[mi], bhi[ni]);
                }
        }
        __syncthreads();
    }

    #pragma unroll
    for (int mi = 0; mi < 4; ++mi) {
        int rm = m0 + wm * 64 + mi * 16 + g;
        #pragma unroll
        for (int ni = 0; ni < 4; ++ni) {
            int cn = n0 + wn * 32 + ni * 8 + 2 * tig;
            *(float2*)(C + (size_t)rm * N + cn) =
                make_float2(acc[mi][ni][0], acc[mi][ni][1]);
            *(float2*)(C + (size_t)(rm + 8) * N + cn) =
                make_float2(acc[mi][ni][2], acc[mi][ni][3]);
        }
    }
}

// ---------------------------------------------------------------------------
// RoPE (reference semantics)
// ---------------------------------------------------------------------------
__global__ void rope_kernel(float* __restrict__ X,
                            const float* __restrict__ cosb,
                            const float* __restrict__ sinb, int nheads)
{
    int idx = blockIdx.x * blockDim.x + threadIdx.x;
    int half = idx & 63;
    int s = (idx >> 6) / nheads % S;
    size_t base = (size_t)(idx >> 6) * HD;
    float x0 = X[base + half];
    float x1 = X[base + half + 64];
    float c0 = cosb[s * 64 + (half >> 1)];
    float s0 = sinb[s * 64 + (half >> 1)];
    float c1 = cosb[s * 64 + ((half + 64) >> 1)];
    float s1 = sinb[s * 64 + ((half + 64) >> 1)];
    X[base + half]      = x0 * c0 - x1 * s0;
    X[base + half + 64] = x1 * c1 + x0 * s1;
}

// ---------------------------------------------------------------------------
// HMMA flash attention: FM=128 q-rows/CTA, FN=64 keys/tile, 256 threads.
// bf16x3 split for both QK^T and PV. Q pre-scaled by SCALE.
// ---------------------------------------------------------------------------
#define QSF 136               // bf16 row stride for 128-wide tiles
#define SSTR 65               // fp32 stride for S
#define PSTR 72               // bf16 stride for P

#define OFF_QHI 0
#define OFF_QLO (OFF_QHI + 128*QSF*2)          // 34816
#define OFF_KHI (OFF_QLO + 128*QSF*2)          // 69632
#define OFF_KLO (OFF_KHI + 64*QSF*2)           // 87040
#define OFF_VHI (OFF_KLO + 64*QSF*2)           // 104448
#define OFF_VLO (OFF_VHI + 64*QSF*2)           // 121856
#define OFF_S   (OFF_VLO + 64*QSF*2)           // 139264
#define OFF_PHI (OFF_S   + 128*SSTR*4)         // 172544
#define OFF_PLO (OFF_PHI + 128*PSTR*2)         // 190976
#define OFF_MR  (OFF_PLO + 128*PSTR*2)         // 209408
#define OFF_LR  (OFF_MR + 128*4)
#define OFF_CR  (OFF_LR + 128*4)
#define FLASH_SMEM (OFF_CR + 128*4)            // 210944 bytes

__global__ __launch_bounds__(256, 1) void flash_hmma_kernel(
    const __nv_bfloat16* __restrict__ Qhi, const __nv_bfloat16* __restrict__ Qlo,
    const __nv_bfloat16* __restrict__ Khi, const __nv_bfloat16* __restrict__ Klo,
    const __nv_bfloat16* __restrict__ Vhi, const __nv_bfloat16* __restrict__ Vlo,
    float* __restrict__ Og)
{
    const int m_tile = blockIdx.x;
    const int h = blockIdx.y;
    const int b = blockIdx.z;
    const int kvh = h / GROUPS;
    const int tid = threadIdx.x;
    const int warp = tid >> 5, lane = tid & 31;
    const int g = lane >> 2, tig = lane & 3;
    const int m0 = m_tile * 128;
    const int wrow = warp * 16;

    extern __shared__ char smc[];
    const uint32_t base = smem_u32(smc);
    float* Ss   = (float*)(smc + OFF_S);
    float* mrow = (float*)(smc + OFF_MR);
    float* lrow = (float*)(smc + OFF_LR);
    float* crow = (float*)(smc + OFF_CR);

    // ldmatrix per-lane offset (elements) into V tile
    const uint32_t voff = (uint32_t)(((lane & 7) + ((lane >> 3) & 1) * 8) * QSF
                                     + (lane >> 4) * 8);

    // ---- load Q tile (hi/lo) via cp.async: 2 mats x 128 rows x 16 chunks ----
    #pragma unroll
    for (int i = 0; i < 16; ++i) {
        int v = i * 256 + tid;            // 0..4095
        int mat = v >> 11;                // 0..1
        int r = (v >> 4) & 127;
        int ch = v & 15;
        const __nv_bfloat16* src = (mat ? Qlo : Qhi)
            + (((size_t)b * S + m0 + r) * H + h) * HD + ch * 8;
        uint32_t dst = base + (mat ? OFF_QLO : OFF_QHI) + (r * QSF + ch * 8) * 2;
        cp16(dst, src);
    }
    CP_COMMIT();
    if (tid < 128) { mrow[tid] = -INFINITY; lrow[tid] = 0.f; }

    float acc[16][4];
    #pragma unroll
    for (int ni = 0; ni < 16; ++ni)
        #pragma unroll
        for (int r = 0; r < 4; ++r) acc[ni][r] = 0.f;

    const int ntmax = 2 * m_tile + 1;
    for (int nt = 0; nt <= ntmax; ++nt) {
        const int n0 = nt * 64;
        __syncthreads();   // protect K/V smem from prev-tile readers

        // ---- load K,V (hi/lo): 4 mats x 64 rows x 16 chunks ----
        const __nv_bfloat16* kvsrc[4] = {Khi, Klo, Vhi, Vlo};
        #pragma unroll
        for (int i = 0; i < 16; ++i) {
            int v = i * 256 + tid;
            int mat = v >> 10;            // 0..3
            int r = (v >> 4) & 63;
            int ch = v & 15;
            const __nv_bfloat16* src = kvsrc[mat]
                + (((size_t)b * S + n0 + r) * KVH + kvh) * HD + ch * 8;
            uint32_t dst = base + OFF_KHI + mat * (64 * QSF * 2)
                           + (r * QSF + ch * 8) * 2;
            cp16(dst, src);
        }
        CP_COMMIT();
        CP_WAIT(0);
        __syncthreads();

        // ---- S = Q @ K^T (3-pass split) ----
        {
            float cs[8][4];
            #pragma unroll
            for (int ni = 0; ni < 8; ++ni)
                #pragma unroll
                for (int r = 0; r < 4; ++r) cs[ni][r] = 0.f;

            const __nv_bfloat16* Q0 = (const __nv_bfloat16*)(smc + OFF_QHI);
            const __nv_bfloat16* Q1 = (const __nv_bfloat16*)(smc + OFF_QLO);
            const __nv_bfloat16* K0 = (const __nv_bfloat16*)(smc + OFF_KHI);
            const __nv_bfloat16* K1 = (const __nv_bfloat16*)(smc + OFF_KLO);

            #pragma unroll
            for (int ks = 0; ks < 8; ++ks) {
                const int kk = ks * 16 + 2 * tig;
                uint32_t ahi[4], alo[4];
                const int rm = wrow + g;
                ahi[0] = *(const uint32_t*)(Q0 + rm * QSF + kk);
                ahi[1] = *(const uint32_t*)(Q0 + (rm + 8) * QSF + kk);
                ahi[2] = *(const uint32_t*)(Q0 + rm * QSF + kk + 8);
                ahi[3] = *(const uint32_t*)(Q0 + (rm + 8) * QSF + kk + 8);
                alo[0] = *(const uint32_t*)(Q1 + rm * QSF + kk);
                alo[1] = *(const uint32_t*)(Q1 + (rm + 8) * QSF + kk);
                alo[2] = *(const uint32_t*)(Q1 + rm * QSF + kk + 8);
                alo[3] = *(const uint32_t*)(Q1 + (rm + 8) * QSF + kk + 8);
                #pragma unroll
                for (int ni = 0; ni < 8; ++ni) {
                    const int cn = ni * 8 + g;
                    uint32_t bhi[2], blo[2];
                    bhi[0] = *(const uint32_t*)(K0 + cn * QSF + kk);
                    bhi[1] = *(const uint32_t*)(K0 + cn * QSF + kk + 8);
                    blo[0] = *(const uint32_t*)(K1 + cn * QSF + kk);
                    blo[1] = *(const uint32_t*)(K1 + cn * QSF + kk + 8);
                    mma16816(cs[ni], ahi, bhi);
                    mma16816(cs[ni], ahi, blo);
                    mma16816(cs[ni], alo, bhi);
                }
            }
            #pragma unroll
            for (int ni = 0; ni < 8; ++ni) {
                const int row = wrow + g, col = ni * 8 + 2 * tig;
                Ss[row * SSTR + col]       = cs[ni][0];
                Ss[row * SSTR + col + 1]   = cs[ni][1];
                Ss[(row + 8) * SSTR + col]     = cs[ni][2];
                Ss[(row + 8) * SSTR + col + 1] = cs[ni][3];
            }
        }
        __syncthreads();

        // ---- softmax + P split (one row per thread, tid<128) ----
        if (tid < 128) {
            const int r = tid;
            const int q = m0 + r;
            int climit = q - n0 + 1;
            climit = climit < 0 ? 0 : (climit > 64 ? 64 : climit);
            __nv_bfloat16* Ph = (__nv_bfloat16*)(smc + OFF_PHI) + r * PSTR;
            __nv_bfloat16* Pl = (__nv_bfloat16*)(smc + OFF_PLO) + r * PSTR;
            if (climit == 0) {
                crow[r] = 1.f;
                #pragma unroll
                for (int c = 0; c < 64; c += 8) {
                    *(uint4*)(Ph + c) = make_uint4(0, 0, 0, 0);
                    *(uint4*)(Pl + c) = make_uint4(0, 0, 0, 0);
                }
            } else {
                float mprev = mrow[r];
                float mx = mprev;
                for (int c = 0; c < climit; ++c)
                    mx = fmaxf(mx, Ss[r * SSTR + c]);
                float corr = __expf(mprev - mx);
                float sum = 0.f;
                for (int c = 0; c < 64; ++c) {
                    float p = (c < climit) ? __expf(Ss[r * SSTR + c] - mx) : 0.f;
                    __nv_bfloat16 ph = __float2bfloat16_rn(p);
                    Ph[c] = ph;
                    Pl[c] = __float2bfloat16_rn(p - __bfloat162float(ph));
                    sum += p;
                }
                lrow[r] = lrow[r] * corr + sum;
                mrow[r] = mx;
                crow[r] = corr;
            }
        }
        __syncthreads();

        // ---- O = O*corr + P @ V (3-pass split) ----
        {
            const float corr0 = crow[wrow + g];
            const float corr1 = crow[wrow + g + 8];
            #pragma unroll
            for (int ni = 0; ni < 16; ++ni) {
                acc[ni][0] *= corr0; acc[ni][1] *= corr0;
                acc[ni][2] *= corr1; acc[ni][3] *= corr1;
            }
            const __nv_bfloat16* Ph = (const __nv_bfloat16*)(smc + OFF_PHI);
            const __nv_bfloat16* Pl = (const __nv_bfloat16*)(smc + OFF_PLO);
            #pragma unroll
            for (int ks = 0; ks < 4; ++ks) {
                const int kk = ks * 16 + 2 * tig;
                uint32_t aph[4], apl[4];
                const int rm = wrow + g;
                aph[0] = *(const uint32_t*)(Ph + rm * PSTR + kk);
                aph[1] = *(const uint32_t*)(Ph + (rm + 8) * PSTR + kk);
                aph[2] = *(const uint32_t*)(Ph + rm * PSTR + kk + 8);
                aph[3] = *(const uint32_t*)(Ph + (rm + 8) * PSTR + kk + 8);
                apl[0] = *(const uint32_t*)(Pl + rm * PSTR + kk);
                apl[1] = *(const uint32_t*)(Pl + (rm + 8) * PSTR + kk);
                apl[2] = *(const uint32_t*)(Pl + rm * PSTR + kk + 8);
                apl[3] = *(const uint32_t*)(Pl + (rm + 8) * PSTR + kk + 8);
                #pragma unroll
                for (int np = 0; np < 8; ++np) {
                    uint32_t bh[4], bl[4];
                    uint32_t va = (uint32_t)(voff + ks * 16 * QSF + np * 16) * 2;
                    ldmx4t(bh, base + OFF_VHI + va);
                    ldmx4t(bl, base + OFF_VLO + va);
                    mma16816(acc[2 * np],     aph, bh);
                    mma16816(acc[2 * np],     aph, bl);
                    mma16816(acc[2 * np],     apl, bh);
                    mma16816(acc[2 * np + 1], aph, bh + 2);
                    mma16816(acc[2 * np + 1], aph, bl + 2);
                    mma16816(acc[2 * np + 1], apl, bh + 2);
                }
            }
        }
    }

    // ---- epilogue: normalize and store ----
    const float inv0 = 1.f / lrow[wrow + g];
    const float inv1 = 1.f / lrow[wrow + g + 8];
    #pragma unroll
    for (int ni = 0; ni < 16; ++ni) {
        const int row = m0 + wrow + g;
        const int col = ni * 8 + 2 * tig;
        *(float2*)(Og + (((size_t)b * S + row) * H + h) * HD + col) =
            make_float2(acc[ni][0] * inv0, acc[ni][1] * inv0);
        *(float2*)(Og + (((size_t)b * S + row + 8) * H + h) * HD + col) =
            make_float2(acc[ni][2] * inv1, acc[ni][3] * inv1);
    }
}

// ---------------------------------------------------------------------------
extern "C" void kernel_launch(void* const* d_in, const int* in_sizes, int n_in,
                              void* d_out, int out_size)
{
    const float* x    = (const float*)d_in[0];
    const float* cosb = (const float*)d_in[1];
    const float* sinb = (const float*)d_in[2];
    const float* Wq   = (const float*)d_in[4];
    const float* Wk   = (const float*)d_in[5];
    const float* Wv   = (const float*)d_in[6];
    const float* Wo   = (const float*)d_in[7];
    float* out = (float*)d_out;

    float *Qp, *Kp, *Vp, *Op;
    cudaGetSymbolAddress((void**)&Qp, g_Q);
    cudaGetSymbolAddress((void**)&Kp, g_K);
    cudaGetSymbolAddress((void**)&Vp, g_V);
    cudaGetSymbolAddress((void**)&Op, g_O);
    __nv_bfloat16 *xhi, *xlo, *ohi, *olo;
    __nv_bfloat16 *wqh, *wql, *wkh, *wkl, *wvh, *wvl, *woh, *wol;
    __nv_bfloat16 *qhi, *qlo, *khi, *klo, *vhi, *vlo;
    cudaGetSymbolAddress((void**)&xhi, g_xhi);
    cudaGetSymbolAddress((void**)&xlo, g_xlo);
    cudaGetSymbolAddress((void**)&ohi, g_ohi);
    cudaGetSymbolAddress((void**)&olo, g_olo);
    cudaGetSymbolAddress((void**)&wqh, g_WqT_hi);
    cudaGetSymbolAddress((void**)&wql, g_WqT_lo);
    cudaGetSymbolAddress((void**)&wkh, g_WkT_hi);
    cudaGetSymbolAddress((void**)&wkl, g_WkT_lo);
    cudaGetSymbolAddress((void**)&wvh, g_WvT_hi);
    cudaGetSymbolAddress((void**)&wvl, g_WvT_lo);
    cudaGetSymbolAddress((void**)&woh, g_WoT_hi);
    cudaGetSymbolAddress((void**)&wol, g_WoT_lo);
    cudaGetSymbolAddress((void**)&qhi, g_Qhi);
    cudaGetSymbolAddress((void**)&qlo, g_Qlo);
    cudaGetSymbolAddress((void**)&khi, g_Khi);
    cudaGetSymbolAddress((void**)&klo, g_Klo);
    cudaGetSymbolAddress((void**)&vhi, g_Vhi);
    cudaGetSymbolAddress((void**)&vlo, g_Vlo);

    const int M = M_ROWS;  // 4096

    // split inputs / transpose+split weights
    split_kernel<<<(M * D / 4) / 256, 256>>>(x, xhi, xlo, M * D / 4);
    transpose_split_kernel<<<dim3(D / 32, D / 32), dim3(32, 8)>>>(Wq, wqh, wql, D, H * HD);
    transpose_split_kernel<<<dim3((KVH * HD) / 32, D / 32), dim3(32, 8)>>>(Wk, wkh, wkl, D, KVH * HD);
    transpose_split_kernel<<<dim3((KVH * HD) / 32, D / 32), dim3(32, 8)>>>(Wv, wvh, wvl, D, KVH * HD);
    transpose_split_kernel<<<dim3(D / 32, (H * HD) / 32), dim3(32, 8)>>>(Wo, woh, wol, H * HD, D);

    cudaFuncSetAttribute(gemm_bf16x3_kernel,
                         cudaFuncAttributeMaxDynamicSharedMemorySize, GEMM_SMEM);

    // QKV projections on HMMA tensor cores
    gemm_bf16x3_kernel<<<dim3((H * HD) / 128, M / 128), 256, GEMM_SMEM>>>(
        Qp, xhi, xlo, wqh, wql, M, H * HD, D);
    gemm_bf16x3_kernel<<<dim3((KVH * HD) / 128, M / 128), 256, GEMM_SMEM>>>(
        Kp, xhi, xlo, wkh, wkl, M, KVH * HD, D);
    gemm_bf16x3_kernel<<<dim3((KVH * HD) / 128, M / 128), 256, GEMM_SMEM>>>(
        Vp, xhi, xlo, wvh, wvl, M, KVH * HD, D);

    // RoPE on fp32 Q/K
    rope_kernel<<<(B * S * H * 64) / 256, 256>>>(Qp, cosb, sinb, H);
    rope_kernel<<<(B * S * KVH * 64) / 256, 256>>>(Kp, cosb, sinb, KVH);

    // split Q (scaled), K, V to bf16 hi/lo for flash
    split_scale_kernel<<<(B * S * H * HD / 4) / 256, 256>>>(
        Qp, qhi, qlo, SCALE, B * S * H * HD / 4);
    split_kernel<<<(B * S * KVH * HD / 4) / 256, 256>>>(
        Kp, khi, klo, B * S * KVH * HD / 4);
    split_kernel<<<(B * S * KVH * HD / 4) / 256, 256>>>(
        Vp, vhi, vlo, B * S * KVH * HD / 4);

    // HMMA causal GQA flash attention
    cudaFuncSetAttribute(flash_hmma_kernel,
                         cudaFuncAttributeMaxDynamicSharedMemorySize, FLASH_SMEM);
    flash_hmma_kernel<<<dim3(S / 128, H, B), 256, FLASH_SMEM>>>(
        qhi, qlo, khi, klo, vhi, vlo, Op);

    // Output projection on HMMA tensor cores
    split_kernel<<<(M * D / 4) / 256, 256>>>(Op, ohi, olo, M * D / 4);
    gemm_bf16x3_kernel<<<dim3(D / 128, M / 128), 256, GEMM_SMEM>>>(
        out, ohi, olo, woh, wol, M, D, D);
}

// round 7
// speedup vs baseline: 3.8952x; 1.3392x over previous
#include <cuda_runtime.h>
#include <cuda_bf16.h>
#include <math.h>
#include <stdint.h>

#define B 2
#define S 2048
#define D 2048
#define H 16
#define KVH 4
#define HD 128
#define GROUPS (H/KVH)
#define SCALE 0.08838834764831845f
#define M_ROWS (B*S)          // 4096

// ---------------- scratch (__device__ globals; no allocation) --------------
__device__ float g_Q[B*S*H*HD];
__device__ float g_K[B*S*KVH*HD];

__device__ __nv_bfloat16 g_xhi[M_ROWS*D],  g_xlo[M_ROWS*D];
__device__ __nv_bfloat16 g_ohi[M_ROWS*D],  g_olo[M_ROWS*D];
__device__ __nv_bfloat16 g_WqT_hi[D*H*HD],   g_WqT_lo[D*H*HD];
__device__ __nv_bfloat16 g_WkT_hi[D*KVH*HD], g_WkT_lo[D*KVH*HD];
__device__ __nv_bfloat16 g_WvT_hi[D*KVH*HD], g_WvT_lo[D*KVH*HD];
__device__ __nv_bfloat16 g_WoT_hi[D*H*HD],   g_WoT_lo[D*H*HD];

__device__ __nv_bfloat16 g_Qhi[B*S*H*HD],   g_Qlo[B*S*H*HD];
__device__ __nv_bfloat16 g_Khi[B*S*KVH*HD], g_Klo[B*S*KVH*HD];
__device__ __nv_bfloat16 g_Vhi[B*S*KVH*HD], g_Vlo[B*S*KVH*HD];

// ---------------------------- helpers --------------------------------------
__device__ __forceinline__ uint32_t smem_u32(const void* p) {
    uint32_t a;
    asm("{ .reg .u64 t; cvta.to.shared.u64 t, %1; cvt.u32.u64 %0, t; }"
        : "=r"(a) : "l"(p));
    return a;
}
__device__ __forceinline__ void cp16(uint32_t s, const void* g) {
    asm volatile("cp.async.cg.shared.global [%0], [%1], 16;" :: "r"(s), "l"(g));
}
#define CP_COMMIT() asm volatile("cp.async.commit_group;" ::: "memory")
#define CP_WAIT(n)  asm volatile("cp.async.wait_group %0;" :: "n"(n) : "memory")

__device__ __forceinline__ void mma16816(float* c, const uint32_t* a,
                                         const uint32_t* b) {
    asm volatile(
        "mma.sync.aligned.m16n8k16.row.col.f32.bf16.bf16.f32 "
        "{%0,%1,%2,%3}, {%4,%5,%6,%7}, {%8,%9}, {%0,%1,%2,%3};"
        : "+f"(c[0]), "+f"(c[1]), "+f"(c[2]), "+f"(c[3])
        : "r"(a[0]), "r"(a[1]), "r"(a[2]), "r"(a[3]), "r"(b[0]), "r"(b[1]));
}
__device__ __forceinline__ void ldmx4(uint32_t* r, uint32_t addr) {
    asm volatile("ldmatrix.sync.aligned.m8n8.x4.shared.b16 {%0,%1,%2,%3}, [%4];"
        : "=r"(r[0]), "=r"(r[1]), "=r"(r[2]), "=r"(r[3]) : "r"(addr));
}
__device__ __forceinline__ void ldmx4t(uint32_t* r, uint32_t addr) {
    asm volatile("ldmatrix.sync.aligned.m8n8.x4.trans.shared.b16 "
                 "{%0,%1,%2,%3}, [%4];"
        : "=r"(r[0]), "=r"(r[1]), "=r"(r[2]), "=r"(r[3]) : "r"(addr));
}
__device__ __forceinline__ uint32_t packbf(float lo_e, float hi_e) {
    uint32_t d;
    asm("cvt.rn.bf16x2.f32 %0, %1, %2;" : "=r"(d) : "f"(hi_e), "f"(lo_e));
    return d;
}
__device__ __forceinline__ float bf16hi(float x) {
    return __bfloat162float(__float2bfloat16_rn(x));
}

// ---------------------------------------------------------------------------
// split: fp32 -> (hi, lo) bf16
// ---------------------------------------------------------------------------
__global__ void split_kernel(const float* __restrict__ X,
                             __nv_bfloat16* __restrict__ hi,
                             __nv_bfloat16* __restrict__ lo, int n4)
{
    int i = blockIdx.x * blockDim.x + threadIdx.x;
    if (i >= n4) return;
    float4 x = reinterpret_cast<const float4*>(X)[i];
    __nv_bfloat16 h[4], l[4];
    float xs[4] = {x.x, x.y, x.z, x.w};
    #pragma unroll
    for (int k = 0; k < 4; k++) {
        h[k] = __float2bfloat16_rn(xs[k]);
        l[k] = __float2bfloat16_rn(xs[k] - __bfloat162float(h[k]));
    }
    *reinterpret_cast<uint2*>(hi + 4*(size_t)i) = *reinterpret_cast<uint2*>(h);
    *reinterpret_cast<uint2*>(lo + 4*(size_t)i) = *reinterpret_cast<uint2*>(l);
}

// ---------------------------------------------------------------------------
// rope + split (+ optional scale): fp32 [B,S,nh,HD] -> bf16 hi/lo
// ---------------------------------------------------------------------------
__global__ void rope_split_kernel(const float* __restrict__ X,
                                  const float* __restrict__ cosb,
                                  const float* __restrict__ sinb,
                                  __nv_bfloat16* __restrict__ hi,
                                  __nv_bfloat16* __restrict__ lo,
                                  float scale, int nheads)
{
    int idx = blockIdx.x * blockDim.x + threadIdx.x;
    int half = idx & 63;
    int s = (idx >> 6) / nheads % S;
    size_t base = (size_t)(idx >> 6) * HD;
    float x0 = X[base + half];
    float x1 = X[base + half + 64];
    float c0 = cosb[s * 64 + (half >> 1)];
    float s0 = sinb[s * 64 + (half >> 1)];
    float c1 = cosb[s * 64 + ((half + 64) >> 1)];
    float s1 = sinb[s * 64 + ((half + 64) >> 1)];
    float y0 = (x0 * c0 - x1 * s0) * scale;
    float y1 = (x1 * c1 + x0 * s1) * scale;
    float h0 = bf16hi(y0), h1 = bf16hi(y1);
    hi[base + half]      = __float2bfloat16_rn(h0);
    hi[base + half + 64] = __float2bfloat16_rn(h1);
    lo[base + half]      = __float2bfloat16_rn(y0 - h0);
    lo[base + half + 64] = __float2bfloat16_rn(y1 - h1);
}

// ---------------------------------------------------------------------------
// transpose + split: W [R, C] fp32 row-major -> T{hi,lo} [C, R] bf16
// ---------------------------------------------------------------------------
__global__ void transpose_split_kernel(const float* __restrict__ W,
                                       __nv_bfloat16* __restrict__ Thi,
                                       __nv_bfloat16* __restrict__ Tlo,
                                       int R, int C)
{
    __shared__ float t[32][33];
    int c0 = blockIdx.x * 32, r0 = blockIdx.y * 32;
    int tx = threadIdx.x, ty = threadIdx.y;
    #pragma unroll
    for (int i = 0; i < 32; i += 8)
        t[ty + i][tx] = W[(size_t)(r0 + ty + i) * C + c0 + tx];
    __syncthreads();
    #pragma unroll
    for (int i = 0; i < 32; i += 8) {
        float x = t[tx][ty + i];
        size_t o = (size_t)(c0 + ty + i) * R + r0 + tx;
        __nv_bfloat16 h = __float2bfloat16_rn(x);
        Thi[o] = h;
        Tlo[o] = __float2bfloat16_rn(x - __bfloat162float(h));
    }
}

// ---------------------------------------------------------------------------
// HMMA bf16x3 GEMM with ldmatrix fragment loads (conflict-free).
// CTA 128x128, BK=64, 8 warps (2x4), 2-stage cp.async.
// If Shi != nullptr: write bf16 hi/lo split instead of fp32 C.
// ---------------------------------------------------------------------------
#define ASTR 72
#define MAT_SZ (128*ASTR)
#define STG_SZ (4*MAT_SZ)
#define GEMM_SMEM (2*STG_SZ*2)

__global__ __launch_bounds__(256, 1)
void gemm_bf16x3_kernel(float* __restrict__ C,
    __nv_bfloat16* __restrict__ Shi, __nv_bfloat16* __restrict__ Slo,
    const __nv_bfloat16* __restrict__ Ahi, const __nv_bfloat16* __restrict__ Alo,
    const __nv_bfloat16* __restrict__ Bhi, const __nv_bfloat16* __restrict__ Blo,
    int M, int N, int K)
{
    extern __shared__ __nv_bfloat16 smb[];
    const uint32_t smem_base = smem_u32(smb);
    const int tid = threadIdx.x;
    const int wid = tid >> 5, lane = tid & 31;
    const int g = lane >> 2, tig = lane & 3;
    const int wm = wid >> 2, wn = wid & 3;
    const int m0 = blockIdx.y * 128, n0 = blockIdx.x * 128;
    const int nch = K >> 6;

    // ldmatrix lane selectors
    const int rowselA = ((lane >> 3) & 1) * 8 + (lane & 7);
    const int colselA = ((lane >> 4) & 1) * 8;
    const int bcolsel = ((lane >> 4) & 1) * 8 + (lane & 7);
    const int bksel   = ((lane >> 3) & 1) * 8;

    const __nv_bfloat16* gsrc[4] = {Ahi, Alo, Bhi, Blo};

    auto load_chunk = [&](int c, int stage) {
        const int k0 = c << 6;
        #pragma unroll
        for (int i = 0; i < 16; ++i) {
            int v = i * 256 + tid;
            int mat = v >> 10;
            int r = (v >> 3) & 127;
            int ch = v & 7;
            int grow = (mat < 2 ? m0 : n0) + r;
            const __nv_bfloat16* src = gsrc[mat] + (size_t)grow * K + k0 + ch * 8;
            uint32_t dst = smem_base +
                (uint32_t)(stage * STG_SZ + mat * MAT_SZ + r * ASTR + ch * 8) * 2;
            cp16(dst, src);
        }
    };

    float acc[4][4][4];
    #pragma unroll
    for (int mi = 0; mi < 4; mi++)
        #pragma unroll
        for (int ni = 0; ni < 4; ni++)
            #pragma unroll
            for (int r = 0; r < 4; r++) acc[mi][ni][r] = 0.f;

    load_chunk(0, 0);
    CP_COMMIT();

    for (int c = 0; c < nch; ++c) {
        if (c + 1 < nch) { load_chunk(c + 1, (c + 1) & 1); CP_COMMIT(); CP_WAIT(1); }
        else             { CP_WAIT(0); }
        __syncthreads();

        const uint32_t stg = smem_base + (uint32_t)((c & 1) * STG_SZ) * 2;
        const uint32_t bAh = stg;
        const uint32_t bAl = stg + (uint32_t)MAT_SZ * 2;
        const uint32_t bBh = stg + (uint32_t)(2 * MAT_SZ) * 2;
        const uint32_t bBl = stg + (uint32_t)(3 * MAT_SZ) * 2;

        #pragma unroll
        for (int ks = 0; ks < 4; ++ks) {
            const int kk0 = ks * 16;
            uint32_t Ah[4][4], Al[4][4], Bh[2][4], Bl[2][4];
            #pragma unroll
            for (int mi = 0; mi < 4; ++mi) {
                uint32_t ar = (uint32_t)((wm * 64 + mi * 16 + rowselA) * ASTR
                                         + kk0 + colselA) * 2;
                ldmx4(Ah[mi], bAh + ar);
                ldmx4(Al[mi], bAl + ar);
            }
            #pragma unroll
            for (int nip = 0; nip < 2; ++nip) {
                uint32_t br = (uint32_t)((wn * 32 + nip * 16 + bcolsel) * ASTR
                                         + kk0 + bksel) * 2;
                ldmx4(Bh[nip], bBh + br);
                ldmx4(Bl[nip], bBl + br);
            }
            #pragma unroll
            for (int mi = 0; mi < 4; ++mi)
                #pragma unroll
                for (int ni = 0; ni < 4; ++ni) {
                    const uint32_t* bh = &Bh[ni >> 1][(ni & 1) * 2];
                    const uint32_t* bl = &Bl[ni >> 1][(ni & 1) * 2];
                    mma16816(acc[mi][ni], Ah[mi], bh);
                    mma16816(acc[mi][ni], Ah[mi], bl);
                    mma16816(acc[mi][ni], Al[mi], bh);
                }
        }
        __syncthreads();
    }

    if (Shi) {
        #pragma unroll
        for (int mi = 0; mi < 4; ++mi) {
            int rm = m0 + wm * 64 + mi * 16 + g;
            #pragma unroll
            for (int ni = 0; ni < 4; ++ni) {
                int cn = n0 + wn * 32 + ni * 8 + 2 * tig;
                float v0 = acc[mi][ni][0], v1 = acc[mi][ni][1];
                float v2 = acc[mi][ni][2], v3 = acc[mi][ni][3];
                float h0 = bf16hi(v0), h1 = bf16hi(v1);
                float h2 = bf16hi(v2), h3 = bf16hi(v3);
                *(uint32_t*)(Shi + (size_t)rm * N + cn) = packbf(h0, h1);
                *(uint32_t*)(Slo + (size_t)rm * N + cn) = packbf(v0 - h0, v1 - h1);
                *(uint32_t*)(Shi + (size_t)(rm + 8) * N + cn) = packbf(h2, h3);
                *(uint32_t*)(Slo + (size_t)(rm + 8) * N + cn) = packbf(v2 - h2, v3 - h3);
            }
        }
    } else {
        #pragma unroll
        for (int mi = 0; mi < 4; ++mi) {
            int rm = m0 + wm * 64 + mi * 16 + g;
            #pragma unroll
            for (int ni = 0; ni < 4; ++ni) {
                int cn = n0 + wn * 32 + ni * 8 + 2 * tig;
                *(float2*)(C + (size_t)rm * N + cn) =
                    make_float2(acc[mi][ni][0], acc[mi][ni][1]);
                *(float2*)(C + (size_t)(rm + 8) * N + cn) =
                    make_float2(acc[mi][ni][2], acc[mi][ni][3]);
            }
        }
    }
}

// ---------------------------------------------------------------------------
// FA2-style HMMA flash attention.
// FM=128 q-rows/CTA, FN=64 keys/tile, 256 threads (8 warps x 16 rows).
// S and P stay in registers; register softmax via shfl over tig lanes.
// K/V double-buffered via cp.async. Writes bf16 hi/lo O directly.
// ---------------------------------------------------------------------------
#define QSF 136
#define STG_KV (4*64*QSF*2)           // 69632 bytes per stage
#define OFF_KV 69632                  // after Qhi (34816) + Qlo (34816)
#define FLASH_SMEM (OFF_KV + 2*STG_KV)   // 208896 bytes

__global__ __launch_bounds__(256, 1) void flash_hmma_kernel(
    const __nv_bfloat16* __restrict__ Qhi, const __nv_bfloat16* __restrict__ Qlo,
    const __nv_bfloat16* __restrict__ Khi, const __nv_bfloat16* __restrict__ Klo,
    const __nv_bfloat16* __restrict__ Vhi, const __nv_bfloat16* __restrict__ Vlo,
    __nv_bfloat16* __restrict__ Ohi, __nv_bfloat16* __restrict__ Olo)
{
    const int m_tile = blockIdx.x;
    const int h = blockIdx.y;
    const int b = blockIdx.z;
    const int kvh = h / GROUPS;
    const int tid = threadIdx.x;
    const int warp = tid >> 5, lane = tid & 31;
    const int g = lane >> 2, tig = lane & 3;
    const int m0 = m_tile * 128;
    const int wrow = warp * 16;

    extern __shared__ char smc[];
    const uint32_t base = smem_u32(smc);

    // ldmatrix selectors
    const int rowselA = ((lane >> 3) & 1) * 8 + (lane & 7);
    const int colselA = ((lane >> 4) & 1) * 8;
    const int bcolsel = ((lane >> 4) & 1) * 8 + (lane & 7);
    const int bksel   = ((lane >> 3) & 1) * 8;
    const uint32_t voff = (uint32_t)(((lane & 7) + ((lane >> 3) & 1) * 8) * QSF
                                     + (lane >> 4) * 8);

    const __nv_bfloat16* kvsrc[4] = {Khi, Klo, Vhi, Vlo};
    auto load_kv = [&](int nt, int stage) {
        const int n0 = nt * 64;
        const uint32_t sb = base + OFF_KV + (uint32_t)stage * STG_KV;
        #pragma unroll
        for (int i = 0; i < 16; ++i) {
            int v = i * 256 + tid;
            int mat = v >> 10;
            int r = (v >> 4) & 63;
            int ch = v & 15;
            const __nv_bfloat16* src = kvsrc[mat]
                + (((size_t)b * S + n0 + r) * KVH + kvh) * HD + ch * 8;
            cp16(sb + (uint32_t)(mat * (64 * QSF) + r * QSF + ch * 8) * 2, src);
        }
    };

    // ---- Q tile loads (hi/lo) ----
    #pragma unroll
    for (int i = 0; i < 16; ++i) {
        int v = i * 256 + tid;
        int mat = v >> 11;
        int r = (v >> 4) & 127;
        int ch = v & 15;
        const __nv_bfloat16* src = (mat ? Qlo : Qhi)
            + (((size_t)b * S + m0 + r) * H + h) * HD + ch * 8;
        cp16(base + (uint32_t)(mat * (128 * QSF) + r * QSF + ch * 8) * 2, src);
    }
    load_kv(0, 0);
    CP_COMMIT();

    float acc[16][4];
    #pragma unroll
    for (int ni = 0; ni < 16; ++ni)
        #pragma unroll
        for (int r = 0; r < 4; ++r) acc[ni][r] = 0.f;

    float m_run0 = -1e30f, m_run1 = -1e30f;
    float l_run0 = 0.f, l_run1 = 0.f;

    const int ntmax = 2 * m_tile + 1;
    for (int nt = 0; nt <= ntmax; ++nt) {
        const int n0 = nt * 64;
        if (nt < ntmax) { load_kv(nt + 1, (nt + 1) & 1); CP_COMMIT(); CP_WAIT(1); }
        else            { CP_WAIT(0); }
        __syncthreads();

        const uint32_t kvb = base + OFF_KV + (uint32_t)(nt & 1) * STG_KV;
        const uint32_t bKh = kvb;
        const uint32_t bKl = kvb + (uint32_t)(64 * QSF) * 2;
        const uint32_t bVh = kvb + (uint32_t)(2 * 64 * QSF) * 2;
        const uint32_t bVl = kvb + (uint32_t)(3 * 64 * QSF) * 2;

        // ---- S = Q @ K^T (3-pass split), result in registers ----
        float cs[8][4];
        #pragma unroll
        for (int ni = 0; ni < 8; ++ni)
            #pragma unroll
            for (int r = 0; r < 4; ++r) cs[ni][r] = 0.f;

        #pragma unroll
        for (int ks = 0; ks < 8; ++ks) {
            const int kk0 = ks * 16;
            uint32_t qh[4], ql[4];
            uint32_t ar = (uint32_t)((wrow + rowselA) * QSF + kk0 + colselA) * 2;
            ldmx4(qh, base + ar);
            ldmx4(ql, base + (uint32_t)(128 * QSF) * 2 + ar);
            #pragma unroll
            for (int nip = 0; nip < 4; ++nip) {
                uint32_t kh[4], kl[4];
                uint32_t br = (uint32_t)((nip * 16 + bcolsel) * QSF + kk0 + bksel) * 2;
                ldmx4(kh, bKh + br);
                ldmx4(kl, bKl + br);
                mma16816(cs[2 * nip],     qh, kh);
                mma16816(cs[2 * nip],     qh, kl);
                mma16816(cs[2 * nip],     ql, kh);
                mma16816(cs[2 * nip + 1], qh, kh + 2);
                mma16816(cs[2 * nip + 1], qh, kl + 2);
                mma16816(cs[2 * nip + 1], ql, kh + 2);
            }
        }

        // ---- causal mask ----
        const int r0g = m0 + wrow + g;
        const int colb = n0 + 2 * tig;
        #pragma unroll
        for (int ni = 0; ni < 8; ++ni) {
            int c = colb + ni * 8;
            if (c > r0g)         cs[ni][0] = -1e30f;
            if (c + 1 > r0g)     cs[ni][1] = -1e30f;
            if (c > r0g + 8)     cs[ni][2] = -1e30f;
            if (c + 1 > r0g + 8) cs[ni][3] = -1e30f;
        }

        // ---- register softmax ----
        float mx0 = -1e30f, mx1 = -1e30f;
        #pragma unroll
        for (int ni = 0; ni < 8; ++ni) {
            mx0 = fmaxf(mx0, fmaxf(cs[ni][0], cs[ni][1]));
            mx1 = fmaxf(mx1, fmaxf(cs[ni][2], cs[ni][3]));
        }
        mx0 = fmaxf(mx0, __shfl_xor_sync(0xFFFFFFFFu, mx0, 1));
        mx0 = fmaxf(mx0, __shfl_xor_sync(0xFFFFFFFFu, mx0, 2));
        mx1 = fmaxf(mx1, __shfl_xor_sync(0xFFFFFFFFu, mx1, 1));
        mx1 = fmaxf(mx1, __shfl_xor_sync(0xFFFFFFFFu, mx1, 2));
        const float mn0 = fmaxf(m_run0, mx0);
        const float mn1 = fmaxf(m_run1, mx1);
        const float corr0 = __expf(m_run0 - mn0);
        const float corr1 = __expf(m_run1 - mn1);
        float sum0 = 0.f, sum1 = 0.f;
        #pragma unroll
        for (int ni = 0; ni < 8; ++ni) {
            cs[ni][0] = __expf(cs[ni][0] - mn0); sum0 += cs[ni][0];
            cs[ni][1] = __expf(cs[ni][1] - mn0); sum0 += cs[ni][1];
            cs[ni][2] = __expf(cs[ni][2] - mn1); sum1 += cs[ni][2];
            cs[ni][3] = __expf(cs[ni][3] - mn1); sum1 += cs[ni][3];
        }
        sum0 += __shfl_xor_sync(0xFFFFFFFFu, sum0, 1);
        sum0 += __shfl_xor_sync(0xFFFFFFFFu, sum0, 2);
        sum1 += __shfl_xor_sync(0xFFFFFFFFu, sum1, 1);
        sum1 += __shfl_xor_sync(0xFFFFFFFFu, sum1, 2);
        l_run0 = l_run0 * corr0 + sum0;
        l_run1 = l_run1 * corr1 + sum1;
        m_run0 = mn0;
        m_run1 = mn1;
        #pragma unroll
        for (int ni = 0; ni < 16; ++ni) {
            acc[ni][0] *= corr0; acc[ni][1] *= corr0;
            acc[ni][2] *= corr1; acc[ni][3] *= corr1;
        }

        // ---- O += P @ V (3-pass split); P fragments built from cs ----
        #pragma unroll
        for (int kp = 0; kp < 4; ++kp) {
            uint32_t aph[4], apl[4];
            #pragma unroll
            for (int t = 0; t < 4; ++t) {
                int nn = 2 * kp + (t >> 1);
                int j0 = (t & 1) * 2;
                float p0 = cs[nn][j0], p1 = cs[nn][j0 + 1];
                float h0 = bf16hi(p0), h1 = bf16hi(p1);
                aph[t] = packbf(h0, h1);
                apl[t] = packbf(p0 - h0, p1 - h1);
            }
            // reorder: a-frag = {row g klo, row g+8 klo, row g khi, row g+8 khi}
            // t mapping above: t0=(2kp,j0)->row g; t1=(2kp,j2)->row g+8;
            // t2=(2kp+1,j0)->row g (k+8); t3=(2kp+1,j2)->row g+8 (k+8)  -> already correct order
            #pragma unroll
            for (int np = 0; np < 8; ++np) {
                uint32_t bh[4], bl[4];
                uint32_t va = (uint32_t)(voff + kp * 16 * QSF + np * 16) * 2;
                ldmx4t(bh, bVh + va);
                ldmx4t(bl, bVl + va);
                mma16816(acc[2 * np],     aph, bh);
                mma16816(acc[2 * np],     aph, bl);
                mma16816(acc[2 * np],     apl, bh);
                mma16816(acc[2 * np + 1], aph, bh + 2);
                mma16816(acc[2 * np + 1], aph, bl + 2);
                mma16816(acc[2 * np + 1], apl, bh + 2);
            }
        }
        __syncthreads();
    }

    // ---- epilogue: normalize, split to bf16 hi/lo, store ----
    const float inv0 = 1.f / l_run0;
    const float inv1 = 1.f / l_run1;
    const size_t row0 = (size_t)b * S + m0 + wrow + g;
    __nv_bfloat16* oh0 = Ohi + row0 * (H * HD) + h * HD;
    __nv_bfloat16* ol0 = Olo + row0 * (H * HD) + h * HD;
    __nv_bfloat16* oh1 = oh0 + 8 * (size_t)(H * HD);
    __nv_bfloat16* ol1 = ol0 + 8 * (size_t)(H * HD);
    #pragma unroll
    for (int ni = 0; ni < 16; ++ni) {
        int c = ni * 8 + 2 * tig;
        float o0 = acc[ni][0] * inv0, o1 = acc[ni][1] * inv0;
        float o2 = acc[ni][2] * inv1, o3 = acc[ni][3] * inv1;
        float h0 = bf16hi(o0), h1 = bf16hi(o1);
        float h2 = bf16hi(o2), h3 = bf16hi(o3);
        *(uint32_t*)(oh0 + c) = packbf(h0, h1);
        *(uint32_t*)(ol0 + c) = packbf(o0 - h0, o1 - h1);
        *(uint32_t*)(oh1 + c) = packbf(h2, h3);
        *(uint32_t*)(ol1 + c) = packbf(o2 - h2, o3 - h3);
    }
}

// ---------------------------------------------------------------------------
extern "C" void kernel_launch(void* const* d_in, const int* in_sizes, int n_in,
                              void* d_out, int out_size)
{
    const float* x    = (const float*)d_in[0];
    const float* cosb = (const float*)d_in[1];
    const float* sinb = (const float*)d_in[2];
    const float* Wq   = (const float*)d_in[4];
    const float* Wk   = (const float*)d_in[5];
    const float* Wv   = (const float*)d_in[6];
    const float* Wo   = (const float*)d_in[7];
    float* out = (float*)d_out;

    float *Qp, *Kp;
    cudaGetSymbolAddress((void**)&Qp, g_Q);
    cudaGetSymbolAddress((void**)&Kp, g_K);
    __nv_bfloat16 *xhi, *xlo, *ohi, *olo;
    __nv_bfloat16 *wqh, *wql, *wkh, *wkl, *wvh, *wvl, *woh, *wol;
    __nv_bfloat16 *qhi, *qlo, *khi, *klo, *vhi, *vlo;
    cudaGetSymbolAddress((void**)&xhi, g_xhi);
    cudaGetSymbolAddress((void**)&xlo, g_xlo);
    cudaGetSymbolAddress((void**)&ohi, g_ohi);
    cudaGetSymbolAddress((void**)&olo, g_olo);
    cudaGetSymbolAddress((void**)&wqh, g_WqT_hi);
    cudaGetSymbolAddress((void**)&wql, g_WqT_lo);
    cudaGetSymbolAddress((void**)&wkh, g_WkT_hi);
    cudaGetSymbolAddress((void**)&wkl, g_WkT_lo);
    cudaGetSymbolAddress((void**)&wvh, g_WvT_hi);
    cudaGetSymbolAddress((void**)&wvl, g_WvT_lo);
    cudaGetSymbolAddress((void**)&woh, g_WoT_hi);
    cudaGetSymbolAddress((void**)&wol, g_WoT_lo);
    cudaGetSymbolAddress((void**)&qhi, g_Qhi);
    cudaGetSymbolAddress((void**)&qlo, g_Qlo);
    cudaGetSymbolAddress((void**)&khi, g_Khi);
    cudaGetSymbolAddress((void**)&klo, g_Klo);
    cudaGetSymbolAddress((void**)&vhi, g_Vhi);
    cudaGetSymbolAddress((void**)&vlo, g_Vlo);

    const int M = M_ROWS;  // 4096

    // prep: split x, transpose+split weights
    split_kernel<<<(M * D / 4) / 256, 256>>>(x, xhi, xlo, M * D / 4);
    transpose_split_kernel<<<dim3(D / 32, D / 32), dim3(32, 8)>>>(Wq, wqh, wql, D, H * HD);
    transpose_split_kernel<<<dim3((KVH * HD) / 32, D / 32), dim3(32, 8)>>>(Wk, wkh, wkl, D, KVH * HD);
    transpose_split_kernel<<<dim3((KVH * HD) / 32, D / 32), dim3(32, 8)>>>(Wv, wvh, wvl, D, KVH * HD);
    transpose_split_kernel<<<dim3(D / 32, (H * HD) / 32), dim3(32, 8)>>>(Wo, woh, wol, H * HD, D);

    cudaFuncSetAttribute(gemm_bf16x3_kernel,
                         cudaFuncAttributeMaxDynamicSharedMemorySize, GEMM_SMEM);

    // projections
    gemm_bf16x3_kernel<<<dim3((H * HD) / 128, M / 128), 256, GEMM_SMEM>>>(
        Qp, nullptr, nullptr, xhi, xlo, wqh, wql, M, H * HD, D);
    gemm_bf16x3_kernel<<<dim3((KVH * HD) / 128, M / 128), 256, GEMM_SMEM>>>(
        Kp, nullptr, nullptr, xhi, xlo, wkh, wkl, M, KVH * HD, D);
    gemm_bf16x3_kernel<<<dim3((KVH * HD) / 128, M / 128), 256, GEMM_SMEM>>>(
        nullptr, vhi, vlo, xhi, xlo, wvh, wvl, M, KVH * HD, D);   // V: split out

    // rope + split (Q scaled by SCALE)
    rope_split_kernel<<<(B * S * H * 64) / 256, 256>>>(
        Qp, cosb, sinb, qhi, qlo, SCALE, H);
    rope_split_kernel<<<(B * S * KVH * 64) / 256, 256>>>(
        Kp, cosb, sinb, khi, klo, 1.0f, KVH);

    // flash attention (writes bf16 hi/lo O)
    cudaFuncSetAttribute(flash_hmma_kernel,
                         cudaFuncAttributeMaxDynamicSharedMemorySize, FLASH_SMEM);
    flash_hmma_kernel<<<dim3(S / 128, H, B), 256, FLASH_SMEM>>>(
        qhi, qlo, khi, klo, vhi, vlo, ohi, olo);

    // output projection
    gemm_bf16x3_kernel<<<dim3(D / 128, M / 128), 256, GEMM_SMEM>>>(
        out, nullptr, nullptr, ohi, olo, woh, wol, M, D, D);
}